// round 1
// baseline (speedup 1.0000x reference)
#include <cuda_runtime.h>
#include <cstdint>

// Scratch: projections (512x512 f32 each = 1 MB each). __device__ globals per harness rules.
__device__ float g_lig_proj[512 * 512];
__device__ float g_rec_proj[512 * 512];

#define D 512
#define TM 64
#define TN 64
#define TK 16

// C[i,o] = sum_k A[i,k] * W[o, w_off + k]  (+ bias[o] when bias != nullptr)
// A: 512x512 row-major. W: 512x1024 row-major. C: 512x512 row-major.
// grid.z == 0 -> ligand (w_off=0, no bias, C=g_lig_proj)
// grid.z == 1 -> receptor (w_off=512, bias=b, C=g_rec_proj)
__global__ __launch_bounds__(256) void proj_gemm_kernel(
    const float* __restrict__ lig,
    const float* __restrict__ rec,
    const float* __restrict__ W,
    const float* __restrict__ bias)
{
    __shared__ float As[TK][TM];
    __shared__ float Bs[TK][TN];

    const int z = blockIdx.z;
    const float* A = (z == 0) ? lig : rec;
    float* C = (z == 0) ? g_lig_proj : g_rec_proj;
    const int w_off = (z == 0) ? 0 : D;

    const int tx = threadIdx.x;  // 0..15 -> output-feature dim
    const int ty = threadIdx.y;  // 0..15 -> row dim
    const int tid = ty * 16 + tx;
    const int i0 = blockIdx.y * TM;
    const int o0 = blockIdx.x * TN;

    float acc[4][4] = {};

    for (int k0 = 0; k0 < D; k0 += TK) {
        // Load A tile (TM x TK) into As[k][i]
        #pragma unroll
        for (int t = tid; t < TM * TK; t += 256) {
            int r = t >> 4;       // row within tile (TK=16)
            int c = t & 15;       // k within tile
            As[c][r] = A[(i0 + r) * D + k0 + c];
        }
        // Load W tile (TN x TK) into Bs[k][o]
        #pragma unroll
        for (int t = tid; t < TN * TK; t += 256) {
            int r = t >> 4;
            int c = t & 15;
            Bs[c][r] = W[(o0 + r) * (2 * D) + w_off + k0 + c];
        }
        __syncthreads();

        #pragma unroll
        for (int kk = 0; kk < TK; kk++) {
            float a[4], bq[4];
            #pragma unroll
            for (int u = 0; u < 4; u++) a[u] = As[kk][ty * 4 + u];
            #pragma unroll
            for (int v = 0; v < 4; v++) bq[v] = Bs[kk][tx * 4 + v];
            #pragma unroll
            for (int u = 0; u < 4; u++)
                #pragma unroll
                for (int v = 0; v < 4; v++)
                    acc[u][v] += a[u] * bq[v];
        }
        __syncthreads();
    }

    #pragma unroll
    for (int u = 0; u < 4; u++) {
        const int i = i0 + ty * 4 + u;
        #pragma unroll
        for (int v = 0; v < 4; v++) {
            const int o = o0 + tx * 4 + v;
            float val = acc[u][v];
            if (z == 1) val += bias[o];
            C[i * D + o] = val;
        }
    }
}

// out[i, j, :] = lig_proj[i, :] + rec_proj_b[j, :]
// Block = one (i, j) row: 128 threads, each one float4 (512 floats/row).
// Streaming stores (write-once 536MB output -> don't pollute L2).
__global__ __launch_bounds__(128) void pair_add_kernel(float4* __restrict__ out)
{
    const int c = threadIdx.x;           // 0..127
    const int j = blockIdx.x;
    const int i = blockIdx.y;

    const float4* lig = reinterpret_cast<const float4*>(g_lig_proj);
    const float4* rec = reinterpret_cast<const float4*>(g_rec_proj);

    float4 a = __ldg(&lig[i * 128 + c]);
    float4 r = __ldg(&rec[j * 128 + c]);
    float4 o;
    o.x = a.x + r.x;
    o.y = a.y + r.y;
    o.z = a.z + r.z;
    o.w = a.w + r.w;

    __stcs(&out[((size_t)(i * D + j)) * 128 + c], o);
}

extern "C" void kernel_launch(void* const* d_in, const int* in_sizes, int n_in,
                              void* d_out, int out_size)
{
    const float* lig = (const float*)d_in[0];   // (512, 512)
    const float* rec = (const float*)d_in[1];   // (512, 512)
    const float* W   = (const float*)d_in[2];   // (512, 1024)
    const float* b   = (const float*)d_in[3];   // (512,)
    float* out = (float*)d_out;                 // (512, 512, 512)

    dim3 gblk(16, 16);
    dim3 ggrd(D / TN, D / TM, 2);   // 8 x 8 x 2 = 128 blocks, one wave
    proj_gemm_kernel<<<ggrd, gblk>>>(lig, rec, W, b);

    dim3 agrd(D, D);                // (j, i)
    pair_add_kernel<<<agrd, 128>>>(reinterpret_cast<float4*>(out));
}

// round 2
// speedup vs baseline: 1.6606x; 1.6606x over previous
#include <cuda_runtime.h>
#include <cstdint>

__device__ float g_lig_proj[512 * 512];
__device__ float g_rec_proj[512 * 512];

#define D 512
#define BM 64
#define BN 64
#define BK 32
#define JBLK 64

// C[i,o] = sum_k A[i,k] * W[o, w_off + k]  (+ bias[o] for receptor)
__global__ __launch_bounds__(256) void proj_gemm_kernel(
    const float* __restrict__ lig,
    const float* __restrict__ rec,
    const float* __restrict__ W,
    const float* __restrict__ bias)
{
    __shared__ float As[BK][BM];   // As[k][i]
    __shared__ float Bs[BK][BN];   // Bs[k][o]

    const int z = blockIdx.z;
    const float* A = (z == 0) ? lig : rec;
    float* C = (z == 0) ? g_lig_proj : g_rec_proj;
    const int w_off_f4 = (z == 0) ? 0 : (D / 4);   // offset in float4 units within a W row

    const int tx = threadIdx.x;  // 0..15 -> output-feature dim
    const int ty = threadIdx.y;  // 0..15 -> row dim
    const int tid = ty * 16 + tx;
    const int i0 = blockIdx.y * BM;
    const int o0 = blockIdx.x * BN;

    // float4 tile loads: tile is 64 rows x 32 cols = 64 x 8 float4 = 512 float4; 256 threads -> 2 each.
    // Thread t handles float4 index t and t+256.
    const int lr0 = tid >> 3;          // row 0..31 (first half)
    const int lc0 = tid & 7;           // float4-col 0..7
    const float4* A4 = reinterpret_cast<const float4*>(A);
    const float4* W4 = reinterpret_cast<const float4*>(W);

    float acc[4][4] = {};

    for (int k0 = 0; k0 < D; k0 += BK) {
        const int kc4 = k0 / 4;
        // A tile: rows i0+lr0 and i0+lr0+32, cols (k0 + lc0*4 .. +3)
        #pragma unroll
        for (int h = 0; h < 2; h++) {
            int r = lr0 + h * 32;
            float4 v = A4[(size_t)(i0 + r) * (D / 4) + kc4 + lc0];
            As[lc0 * 4 + 0][r] = v.x;
            As[lc0 * 4 + 1][r] = v.y;
            As[lc0 * 4 + 2][r] = v.z;
            As[lc0 * 4 + 3][r] = v.w;
        }
        // W tile: rows o0+lr0 (+32), W row stride = 2D floats = 2D/4 float4
        #pragma unroll
        for (int h = 0; h < 2; h++) {
            int r = lr0 + h * 32;
            float4 v = W4[(size_t)(o0 + r) * (2 * D / 4) + w_off_f4 + kc4 + lc0];
            Bs[lc0 * 4 + 0][r] = v.x;
            Bs[lc0 * 4 + 1][r] = v.y;
            Bs[lc0 * 4 + 2][r] = v.z;
            Bs[lc0 * 4 + 3][r] = v.w;
        }
        __syncthreads();

        #pragma unroll
        for (int kk = 0; kk < BK; kk++) {
            float a[4], bq[4];
            #pragma unroll
            for (int u = 0; u < 4; u++) a[u] = As[kk][ty * 4 + u];
            #pragma unroll
            for (int v = 0; v < 4; v++) bq[v] = Bs[kk][tx * 4 + v];
            #pragma unroll
            for (int u = 0; u < 4; u++)
                #pragma unroll
                for (int v = 0; v < 4; v++)
                    acc[u][v] += a[u] * bq[v];
        }
        __syncthreads();
    }

    #pragma unroll
    for (int u = 0; u < 4; u++) {
        const int i = i0 + ty * 4 + u;
        #pragma unroll
        for (int v = 0; v < 4; v++) {
            const int o = o0 + tx * 4 + v;
            float val = acc[u][v];
            if (z == 1) val += bias[o];
            C[i * D + o] = val;
        }
    }
}

// out[i, j, :] = lig_proj[i, :] + rec_proj[j, :]
// Block = (one i, JBLK consecutive j's), 128 threads (one float4 column each).
// Ligand float4 hoisted to a register; rec rows stream from L2; streaming stores.
__global__ __launch_bounds__(128) void pair_add_kernel(float4* __restrict__ out)
{
    const int c = threadIdx.x;            // 0..127 float4 column
    const int i = blockIdx.y;
    const int j0 = blockIdx.x * JBLK;

    const float4* lig = reinterpret_cast<const float4*>(g_lig_proj);
    const float4* rec = reinterpret_cast<const float4*>(g_rec_proj);

    const float4 a = lig[i * 128 + c];

    const float4* rp = rec + (size_t)j0 * 128 + c;
    float4* op = out + ((size_t)i * D + j0) * 128 + c;

    #pragma unroll 8
    for (int jj = 0; jj < JBLK; jj++) {
        float4 r = __ldg(rp + (size_t)jj * 128);
        float4 o;
        o.x = a.x + r.x;
        o.y = a.y + r.y;
        o.z = a.z + r.z;
        o.w = a.w + r.w;
        __stcs(op + (size_t)jj * 128, o);
    }
}

extern "C" void kernel_launch(void* const* d_in, const int* in_sizes, int n_in,
                              void* d_out, int out_size)
{
    const float* lig = (const float*)d_in[0];   // (512, 512)
    const float* rec = (const float*)d_in[1];   // (512, 512)
    const float* W   = (const float*)d_in[2];   // (512, 1024)
    const float* b   = (const float*)d_in[3];   // (512,)
    float* out = (float*)d_out;                 // (512, 512, 512)

    dim3 gblk(16, 16);
    dim3 ggrd(D / BN, D / BM, 2);   // 8 x 8 x 2 = 128 blocks, one wave
    proj_gemm_kernel<<<ggrd, gblk>>>(lig, rec, W, b);

    dim3 agrd(D / JBLK, D);         // (j-chunk, i) = 8 x 512 = 4096 blocks
    pair_add_kernel<<<agrd, 128>>>(reinterpret_cast<float4*>(out));
}